// round 1
// baseline (speedup 1.0000x reference)
#include <cuda_runtime.h>
#include <math.h>

#define B_ 4
#define T_ 2048
#define C_ 1024
#define H_ 16
#define D_ 64
#define M_ (B_*T_)      // 8192 rows
#define F_ (4*C_)       // 4096 ffn hidden

// ---------------- scratch (device globals; no allocations allowed) ----------
__device__ __align__(256) float g_xn [M_*C_];
__device__ __align__(256) float g_q  [M_*C_];
__device__ __align__(256) float g_k  [M_*C_];
__device__ __align__(256) float g_v  [M_*C_];
__device__ __align__(256) float g_att[M_*C_];
__device__ __align__(256) float g_x1 [M_*C_];
__device__ __align__(256) float g_xn2[M_*C_];
__device__ __align__(256) float g_h  [M_*F_];
__device__ __align__(256) float g_pwq[C_*C_];
__device__ __align__(256) float g_pwk[C_*C_];
__device__ __align__(256) float g_pwv[C_*C_];

// ---------------- LayerNorm: one block per row of 1024 ----------------------
__global__ void ln_kernel(const float* __restrict__ x, const float* __restrict__ g,
                          const float* __restrict__ b, float* __restrict__ out)
{
    const int row = blockIdx.x, tid = threadIdx.x;
    const float4* xr = (const float4*)(x + (size_t)row * C_);
    float4 xv = xr[tid];
    __shared__ float r1[8], r2[8];

    float s = xv.x + xv.y + xv.z + xv.w;
    #pragma unroll
    for (int o = 16; o > 0; o >>= 1) s += __shfl_xor_sync(0xffffffffu, s, o);
    if ((tid & 31) == 0) r1[tid >> 5] = s;
    __syncthreads();
    float tot = r1[0]+r1[1]+r1[2]+r1[3]+r1[4]+r1[5]+r1[6]+r1[7];
    float mu = tot * (1.0f / C_);

    float d0 = xv.x - mu, d1 = xv.y - mu, d2 = xv.z - mu, d3 = xv.w - mu;
    float sq = d0*d0 + d1*d1 + d2*d2 + d3*d3;
    #pragma unroll
    for (int o = 16; o > 0; o >>= 1) sq += __shfl_xor_sync(0xffffffffu, sq, o);
    if ((tid & 31) == 0) r2[tid >> 5] = sq;
    __syncthreads();
    float tots = r2[0]+r2[1]+r2[2]+r2[3]+r2[4]+r2[5]+r2[6]+r2[7];
    float rstd = rsqrtf(tots * (1.0f / C_) + 1e-5f);

    float4 gv = ((const float4*)g)[tid];
    float4 bv = ((const float4*)b)[tid];
    float4 o4;
    o4.x = d0 * rstd * gv.x + bv.x;
    o4.y = d1 * rstd * gv.y + bv.y;
    o4.z = d2 * rstd * gv.z + bv.z;
    o4.w = d3 * rstd * gv.w + bv.w;
    ((float4*)(out + (size_t)row * C_))[tid] = o4;
}

// ------- repack wq/wk/wv [H,C,D] -> [C, H*D] row-major for standard GEMM ----
__global__ void repack_qkv(const float* __restrict__ wq, const float* __restrict__ wk,
                           const float* __restrict__ wv)
{
    int i = blockIdx.x * 256 + threadIdx.x;     // over C_*C_
    int c = i >> 10;
    int n = i & 1023;
    int h = n >> 6;
    int d = n & 63;
    int src = (h * C_ + c) * D_ + d;
    g_pwq[i] = wq[src];
    g_pwk[i] = wk[src];
    g_pwv[i] = wv[src];
}

// ---------------- SGEMM 128x128x8, 256 threads, 8x8 per thread --------------
// EPI bits: 1 = +bias, 2 = relu, 4 = +residual
template<int EPI>
__global__ void __launch_bounds__(256, 2) sgemm128(
    const float* __restrict__ A, const float* __restrict__ Bm,
    float* __restrict__ D, const float* __restrict__ bias,
    const float* __restrict__ res, int M, int N, int K)
{
    __shared__ float As[8][128];   // transposed A tile
    __shared__ float Bs[8][128];
    const int tid = threadIdx.x;
    const int bx = blockIdx.x, by = blockIdx.y;

    const int arow = tid >> 1, acol = (tid & 1) << 2;
    const int brow = tid >> 5, bcol = (tid & 31) << 2;
    const float* Ap = A + (size_t)(by * 128 + arow) * K + acol;
    const float* Bp = Bm + (size_t)brow * N + bx * 128 + bcol;

    const int tr = (tid >> 4) << 2;    // 0..60
    const int tc = (tid & 15) << 2;    // 0..60

    float acc[8][8];
    #pragma unroll
    for (int i = 0; i < 8; i++)
        #pragma unroll
        for (int j = 0; j < 8; j++) acc[i][j] = 0.f;

    for (int k0 = 0; k0 < K; k0 += 8) {
        float4 av = *(const float4*)Ap;
        float4 bv = *(const float4*)Bp;
        Ap += 8; Bp += (size_t)8 * N;
        As[acol + 0][arow] = av.x;
        As[acol + 1][arow] = av.y;
        As[acol + 2][arow] = av.z;
        As[acol + 3][arow] = av.w;
        *(float4*)&Bs[brow][bcol] = bv;
        __syncthreads();
        #pragma unroll
        for (int kk = 0; kk < 8; kk++) {
            float4 a0 = *(const float4*)&As[kk][tr];
            float4 a1 = *(const float4*)&As[kk][tr + 64];
            float4 b0 = *(const float4*)&Bs[kk][tc];
            float4 b1 = *(const float4*)&Bs[kk][tc + 64];
            float ar[8] = {a0.x, a0.y, a0.z, a0.w, a1.x, a1.y, a1.z, a1.w};
            float br[8] = {b0.x, b0.y, b0.z, b0.w, b1.x, b1.y, b1.z, b1.w};
            #pragma unroll
            for (int i = 0; i < 8; i++)
                #pragma unroll
                for (int j = 0; j < 8; j++)
                    acc[i][j] += ar[i] * br[j];
        }
        __syncthreads();
    }

    #pragma unroll
    for (int i = 0; i < 8; i++) {
        int gr = by * 128 + ((i < 4) ? (tr + i) : (64 + tr + i - 4));
        #pragma unroll
        for (int jh = 0; jh < 2; jh++) {
            int gc = bx * 128 + tc + jh * 64;
            float4 o = make_float4(acc[i][jh*4+0], acc[i][jh*4+1],
                                   acc[i][jh*4+2], acc[i][jh*4+3]);
            if (EPI & 1) {
                float4 bb = *(const float4*)(bias + gc);
                o.x += bb.x; o.y += bb.y; o.z += bb.z; o.w += bb.w;
            }
            if (EPI & 2) {
                o.x = fmaxf(o.x, 0.f); o.y = fmaxf(o.y, 0.f);
                o.z = fmaxf(o.z, 0.f); o.w = fmaxf(o.w, 0.f);
            }
            if (EPI & 4) {
                float4 rr = *(const float4*)(res + (size_t)gr * N + gc);
                o.x += rr.x; o.y += rr.y; o.z += rr.z; o.w += rr.w;
            }
            *(float4*)(D + (size_t)gr * N + gc) = o;
        }
    }
}

// ---------------- causal flash attention, 64x64 tiles, D=64 -----------------
// q/k/v layout: [b*T + t][h*64 + d]  (natural GEMM output; concat-free)
// scale = C^-0.5 = 1/32 (reference scales by full embedding dim!)
__global__ void __launch_bounds__(256) attn_kernel(
    const float* __restrict__ Q, const float* __restrict__ Kg,
    const float* __restrict__ V, float* __restrict__ O)
{
    __shared__ float Qs[64][64];   // transposed: Qs[kk][r]
    __shared__ float Ks[64][64];   // transposed: Ks[kk][j]; reused as P[r][j]
    __shared__ float Vs[64][64];   // Vs[j][c]

    const int bh = blockIdx.x, qt = blockIdx.y;
    const int b = bh >> 4, h = bh & 15;
    const size_t base = (size_t)b * T_ * C_ + (size_t)h * 64;
    const float* Qb = Q + base;
    const float* Kb = Kg + base;
    const float* Vb = V + base;

    const int tid = threadIdx.x;
    const int tr = (tid >> 4) << 2;   // 4 rows
    const int tc = (tid & 15) << 2;   // 4 cols

    // load Q tile (transposed)
    #pragma unroll
    for (int i = 0; i < 4; i++) {
        int idx = i * 256 + tid;
        int row = idx >> 4, c4 = (idx & 15) << 2;
        float4 qv = *(const float4*)(Qb + (size_t)(qt * 64 + row) * C_ + c4);
        Qs[c4 + 0][row] = qv.x; Qs[c4 + 1][row] = qv.y;
        Qs[c4 + 2][row] = qv.z; Qs[c4 + 3][row] = qv.w;
    }

    float m[4], l[4], acc[4][4];
    #pragma unroll
    for (int i = 0; i < 4; i++) {
        m[i] = -INFINITY; l[i] = 0.f;
        #pragma unroll
        for (int j = 0; j < 4; j++) acc[i][j] = 0.f;
    }

    for (int kt = 0; kt <= qt; kt++) {
        __syncthreads();   // prior iter done with Ks(P)/Vs; Q store visible (1st iter)
        #pragma unroll
        for (int i = 0; i < 4; i++) {
            int idx = i * 256 + tid;
            int row = idx >> 4, c4 = (idx & 15) << 2;
            float4 kv = *(const float4*)(Kb + (size_t)(kt * 64 + row) * C_ + c4);
            Ks[c4 + 0][row] = kv.x; Ks[c4 + 1][row] = kv.y;
            Ks[c4 + 2][row] = kv.z; Ks[c4 + 3][row] = kv.w;
            float4 vv = *(const float4*)(Vb + (size_t)(kt * 64 + row) * C_ + c4);
            *(float4*)&Vs[row][c4] = vv;
        }
        __syncthreads();

        // S = Q K^T over d=64
        float s[4][4];
        #pragma unroll
        for (int i = 0; i < 4; i++)
            #pragma unroll
            for (int j = 0; j < 4; j++) s[i][j] = 0.f;
        #pragma unroll 16
        for (int kk = 0; kk < 64; kk++) {
            float4 q4 = *(const float4*)&Qs[kk][tr];
            float4 k4 = *(const float4*)&Ks[kk][tc];
            float qa[4] = {q4.x, q4.y, q4.z, q4.w};
            float ka[4] = {k4.x, k4.y, k4.z, k4.w};
            #pragma unroll
            for (int i = 0; i < 4; i++)
                #pragma unroll
                for (int j = 0; j < 4; j++)
                    s[i][j] += qa[i] * ka[j];
        }

        // online softmax across the 16-lane row group
        float p[4][4];
        const float scale = 0.03125f;
        #pragma unroll
        for (int i = 0; i < 4; i++) {
            float mx = -INFINITY;
            #pragma unroll
            for (int j = 0; j < 4; j++) {
                float sv = s[i][j] * scale;
                if (kt == qt && (tc + j) > (tr + i)) sv = -INFINITY;
                s[i][j] = sv;
                mx = fmaxf(mx, sv);
            }
            #pragma unroll
            for (int off = 1; off < 16; off <<= 1)
                mx = fmaxf(mx, __shfl_xor_sync(0xffffffffu, mx, off, 16));
            float mn = fmaxf(m[i], mx);
            float a = __expf(m[i] - mn);
            m[i] = mn;
            float rs = 0.f;
            #pragma unroll
            for (int j = 0; j < 4; j++) {
                float pv = __expf(s[i][j] - mn);
                p[i][j] = pv; rs += pv;
            }
            #pragma unroll
            for (int off = 1; off < 16; off <<= 1)
                rs += __shfl_xor_sync(0xffffffffu, rs, off, 16);
            l[i] = l[i] * a + rs;
            #pragma unroll
            for (int j = 0; j < 4; j++) acc[i][j] *= a;
        }

        // exchange P through the (now-free) K tile buffer
        __syncthreads();   // everyone done reading Ks for S
        #pragma unroll
        for (int i = 0; i < 4; i++)
            *(float4*)&Ks[tr + i][tc] = make_float4(p[i][0], p[i][1], p[i][2], p[i][3]);
        __syncwarp();      // row group (16 lanes) is warp-local

        // O += P @ V
        #pragma unroll 8
        for (int j = 0; j < 64; j++) {
            float4 v4 = *(const float4*)&Vs[j][tc];
            #pragma unroll
            for (int i = 0; i < 4; i++) {
                float pv = Ks[tr + i][j];
                acc[i][0] += pv * v4.x;
                acc[i][1] += pv * v4.y;
                acc[i][2] += pv * v4.z;
                acc[i][3] += pv * v4.w;
            }
        }
    }

    #pragma unroll
    for (int i = 0; i < 4; i++) {
        float inv = 1.0f / l[i];
        float4 o = make_float4(acc[i][0] * inv, acc[i][1] * inv,
                               acc[i][2] * inv, acc[i][3] * inv);
        *(float4*)(O + base + (size_t)(qt * 64 + tr + i) * C_ + tc) = o;
    }
}

// ---------------------------------------------------------------------------
extern "C" void kernel_launch(void* const* d_in, const int* in_sizes, int n_in,
                              void* d_out, int out_size)
{
    const float* x      = (const float*)d_in[0];
    const float* wq     = (const float*)d_in[1];
    const float* wk     = (const float*)d_in[2];
    const float* wv     = (const float*)d_in[3];
    const float* w_proj = (const float*)d_in[4];
    const float* b_proj = (const float*)d_in[5];
    const float* w1     = (const float*)d_in[6];
    const float* b1     = (const float*)d_in[7];
    const float* w2     = (const float*)d_in[8];
    const float* b2     = (const float*)d_in[9];
    const float* g1     = (const float*)d_in[10];
    const float* be1    = (const float*)d_in[11];
    const float* g2     = (const float*)d_in[12];
    const float* be2    = (const float*)d_in[13];
    float* out = (float*)d_out;

    float *xn, *q, *k, *v, *att, *x1, *xn2, *hb, *pwq, *pwk, *pwv;
    cudaGetSymbolAddress((void**)&xn,  g_xn);
    cudaGetSymbolAddress((void**)&q,   g_q);
    cudaGetSymbolAddress((void**)&k,   g_k);
    cudaGetSymbolAddress((void**)&v,   g_v);
    cudaGetSymbolAddress((void**)&att, g_att);
    cudaGetSymbolAddress((void**)&x1,  g_x1);
    cudaGetSymbolAddress((void**)&xn2, g_xn2);
    cudaGetSymbolAddress((void**)&hb,  g_h);
    cudaGetSymbolAddress((void**)&pwq, g_pwq);
    cudaGetSymbolAddress((void**)&pwk, g_pwk);
    cudaGetSymbolAddress((void**)&pwv, g_pwv);

    // LN1
    ln_kernel<<<M_, 256>>>(x, g1, be1, xn);
    // repack QKV weights [H,C,D] -> [C,C]
    repack_qkv<<<(C_ * C_) / 256, 256>>>(wq, wk, wv);
    // QKV projections
    sgemm128<0><<<dim3(C_ / 128, M_ / 128), 256>>>(xn, pwq, q, nullptr, nullptr, M_, C_, C_);
    sgemm128<0><<<dim3(C_ / 128, M_ / 128), 256>>>(xn, pwk, k, nullptr, nullptr, M_, C_, C_);
    sgemm128<0><<<dim3(C_ / 128, M_ / 128), 256>>>(xn, pwv, v, nullptr, nullptr, M_, C_, C_);
    // causal attention
    attn_kernel<<<dim3(B_ * H_, T_ / 64), 256>>>(q, k, v, att);
    // out projection + bias + residual(x)
    sgemm128<5><<<dim3(C_ / 128, M_ / 128), 256>>>(att, w_proj, x1, b_proj, x, M_, C_, C_);
    // LN2
    ln_kernel<<<M_, 256>>>(x1, g2, be2, xn2);
    // FFN1: bias + relu
    sgemm128<3><<<dim3(F_ / 128, M_ / 128), 256>>>(xn2, w1, hb, b1, nullptr, M_, F_, C_);
    // FFN2: bias + residual(x1) -> out
    sgemm128<5><<<dim3(C_ / 128, M_ / 128), 256>>>(hb, w2, out, b2, x1, M_, C_, F_);
}

// round 5
// speedup vs baseline: 2.2858x; 2.2858x over previous
#include <cuda_runtime.h>
#include <math.h>
#include <stdint.h>

#define B_ 4
#define T_ 2048
#define C_ 1024
#define H_ 16
#define D_ 64
#define M_ (B_*T_)      // 8192 rows
#define F_ (4*C_)       // 4096 ffn hidden
#define C3_ 3072        // fused qkv width

// ---------------- scratch (device globals; no allocations allowed) ----------
__device__ __align__(256) float g_xn  [M_*C_];
__device__ __align__(256) float g_qkv [M_*C3_];
__device__ __align__(256) float g_att [M_*C_];
__device__ __align__(256) float g_x1  [M_*C_];
__device__ __align__(256) float g_xn2 [M_*C_];
__device__ __align__(256) float g_h   [M_*F_];
__device__ __align__(256) float g_pw  [C3_*C_];   // fused qkv weights [3072][1024] K-major
__device__ __align__(256) float g_wpt [C_*C_];    // w_proj^T
__device__ __align__(256) float g_w1t [F_*C_];    // w1^T
__device__ __align__(256) float g_w2t [C_*F_];    // w2^T

// ======================= helpers =======================
__device__ __forceinline__ uint32_t smem_u32(const void* p) {
    uint32_t a;
    asm("{ .reg .u64 t; cvta.to.shared.u64 t, %1; cvt.u32.u64 %0, t; }" : "=r"(a) : "l"(p));
    return a;
}
__device__ __forceinline__ float rtf32(float x) {
    uint32_t u;
    asm("cvt.rna.tf32.f32 %0, %1;" : "=r"(u) : "f"(x));
    return __uint_as_float(u);
}
__device__ __forceinline__ void cp16(uint32_t dst, const void* src) {
    asm volatile("cp.async.cg.shared.global [%0], [%1], 16;" :: "r"(dst), "l"(src));
}
__device__ __forceinline__ void mma_tf32_frag(float* c, const uint32_t* a, uint32_t b0, uint32_t b1) {
    asm volatile(
        "mma.sync.aligned.m16n8k8.row.col.f32.tf32.tf32.f32 "
        "{%0,%1,%2,%3}, {%4,%5,%6,%7}, {%8,%9}, {%0,%1,%2,%3};\n"
        : "+f"(c[0]), "+f"(c[1]), "+f"(c[2]), "+f"(c[3])
        : "r"(a[0]), "r"(a[1]), "r"(a[2]), "r"(a[3]), "r"(b0), "r"(b1));
}

// ======================= LayerNorm (rounds output to tf32) =======
__global__ void ln_kernel(const float* __restrict__ x, const float* __restrict__ g,
                          const float* __restrict__ b, float* __restrict__ out)
{
    const int row = blockIdx.x, tid = threadIdx.x;
    float4 xv = ((const float4*)(x + (size_t)row * C_))[tid];
    __shared__ float r1[8], r2[8];

    float s = xv.x + xv.y + xv.z + xv.w;
    #pragma unroll
    for (int o = 16; o > 0; o >>= 1) s += __shfl_xor_sync(0xffffffffu, s, o);
    if ((tid & 31) == 0) r1[tid >> 5] = s;
    __syncthreads();
    float mu = (r1[0]+r1[1]+r1[2]+r1[3]+r1[4]+r1[5]+r1[6]+r1[7]) * (1.0f / C_);

    float d0 = xv.x - mu, d1 = xv.y - mu, d2 = xv.z - mu, d3 = xv.w - mu;
    float sq = d0*d0 + d1*d1 + d2*d2 + d3*d3;
    #pragma unroll
    for (int o = 16; o > 0; o >>= 1) sq += __shfl_xor_sync(0xffffffffu, sq, o);
    if ((tid & 31) == 0) r2[tid >> 5] = sq;
    __syncthreads();
    float rstd = rsqrtf((r2[0]+r2[1]+r2[2]+r2[3]+r2[4]+r2[5]+r2[6]+r2[7]) * (1.0f / C_) + 1e-5f);

    float4 gv = ((const float4*)g)[tid];
    float4 bv = ((const float4*)b)[tid];
    float4 o4;
    o4.x = rtf32(d0 * rstd * gv.x + bv.x);
    o4.y = rtf32(d1 * rstd * gv.y + bv.y);
    o4.z = rtf32(d2 * rstd * gv.z + bv.z);
    o4.w = rtf32(d3 * rstd * gv.w + bv.w);
    ((float4*)(out + (size_t)row * C_))[tid] = o4;
}

// ========== batched transpose: in[b][R][Cc] -> out[(b*Cc + c)*R + r], tf32-rounded ==========
__global__ void transpose_k(const float* __restrict__ in, float* __restrict__ out, int R, int Cc)
{
    __shared__ float t[32][33];
    const int b = blockIdx.z;
    const float* ib = in + (size_t)b * R * Cc;
    float* ob = out + (size_t)b * Cc * R;
    const int c0 = blockIdx.x * 32, r0 = blockIdx.y * 32;
    const int tx = threadIdx.x, ty = threadIdx.y;
    #pragma unroll
    for (int j = 0; j < 32; j += 8)
        t[ty + j][tx] = ib[(size_t)(r0 + ty + j) * Cc + c0 + tx];
    __syncthreads();
    #pragma unroll
    for (int j = 0; j < 32; j += 8)
        ob[(size_t)(c0 + ty + j) * R + r0 + tx] = rtf32(t[tx][ty + j]);
}

// ======================= tf32 mma.sync GEMM =======================
// D[M,N] = A[M,K] @ Bt[N,K]^T ; CTA tile 128x256, 8 warps (2x4), warp tile 64x64
// All A/Bt values must already be exact tf32 (pre-rounded by producers).
// EPI bits: 1=+bias, 2=relu, 4=+residual, 8=round output to tf32
#define BM 128
#define BN 256
#define BKG 32
#define STR 36                  // padded row stride (floats)
#define ABUF (BM*STR)           // A buffer words
#define BUFW ((BM+BN)*STR)      // one stage words = 13824
#define GSMEM (2*BUFW*4)        // 110592 bytes

template<int EPI>
__global__ void __launch_bounds__(256, 1) gemm_mma(
    const float* __restrict__ A, const float* __restrict__ Bt,
    float* __restrict__ Dm, const float* __restrict__ bias,
    const float* __restrict__ res, int M, int N, int K)
{
    extern __shared__ __align__(16) float sm[];
    const uint32_t sbase = smem_u32(sm);
    const int tid = threadIdx.x;
    const int wid = tid >> 5, lane = tid & 31;
    const int wm = (wid >> 2) * 64, wn = (wid & 3) * 64;
    const int g = lane >> 2, t = lane & 3;

    // cp.async slots: 12 x 16B per thread.  slots 0-3 -> A tile, 4-11 -> B tile
    uint32_t gofs[12], sofs[12];
    #pragma unroll
    for (int s = 0; s < 12; s++) {
        int sid = s * 256 + tid;
        if (s < 4) {
            int row = sid >> 3, seg = sid & 7;
            gofs[s] = (uint32_t)((blockIdx.y * BM + row) * K + seg * 4);
            sofs[s] = (uint32_t)((row * STR + seg * 4) * 4);
        } else {
            int row = (sid - 1024) >> 3, seg = sid & 7;
            gofs[s] = (uint32_t)((blockIdx.x * BN + row) * K + seg * 4);
            sofs[s] = (uint32_t)(((BM + row) * STR + seg * 4) * 4);
        }
    }

    float acc[4][8][4];
    #pragma unroll
    for (int i = 0; i < 4; i++)
        #pragma unroll
        for (int j = 0; j < 8; j++)
            #pragma unroll
            for (int q = 0; q < 4; q++) acc[i][j][q] = 0.f;

    const int NIT = K / BKG;

    // prologue: stage 0
    {
        uint32_t db = sbase;
        #pragma unroll
        for (int s = 0; s < 4; s++)  cp16(db + sofs[s], A  + gofs[s]);
        #pragma unroll
        for (int s = 4; s < 12; s++) cp16(db + sofs[s], Bt + gofs[s]);
        asm volatile("cp.async.commit_group;");
    }

    #pragma unroll 1
    for (int it = 0; it < NIT; it++) {
        const int p = it & 1;
        if (it + 1 < NIT) {
            uint32_t db = sbase + (p ^ 1) * (BUFW * 4);
            uint32_t ko = (uint32_t)((it + 1) * BKG);
            #pragma unroll
            for (int s = 0; s < 4; s++)  cp16(db + sofs[s], A  + gofs[s] + ko);
            #pragma unroll
            for (int s = 4; s < 12; s++) cp16(db + sofs[s], Bt + gofs[s] + ko);
        }
        asm volatile("cp.async.commit_group;");
        asm volatile("cp.async.wait_group 1;");
        __syncthreads();

        const float* Ab = sm + p * BUFW;
        const float* Bb = Ab + ABUF;
        #pragma unroll
        for (int ks = 0; ks < 4; ks++) {
            const int k0 = ks * 8 + t;
            uint32_t a[4][4];
            #pragma unroll
            for (int i = 0; i < 4; i++) {
                const float* ap = Ab + (wm + i * 16 + g) * STR + k0;
                a[i][0] = __float_as_uint(ap[0]);
                a[i][1] = __float_as_uint(ap[8 * STR]);
                a[i][2] = __float_as_uint(ap[4]);
                a[i][3] = __float_as_uint(ap[8 * STR + 4]);
            }
            #pragma unroll
            for (int j = 0; j < 8; j++) {
                const float* bp = Bb + (wn + j * 8 + g) * STR + k0;
                uint32_t b0 = __float_as_uint(bp[0]);
                uint32_t b1 = __float_as_uint(bp[4]);
                #pragma unroll
                for (int i = 0; i < 4; i++)
                    mma_tf32_frag(acc[i][j], a[i], b0, b1);
            }
        }
        __syncthreads();
    }

    // epilogue
    #pragma unroll
    for (int i = 0; i < 4; i++) {
        const int m0 = blockIdx.y * BM + wm + i * 16 + g;
        #pragma unroll
        for (int j = 0; j < 8; j++) {
            const int n0 = blockIdx.x * BN + wn + j * 8 + t * 2;
            float2 v0 = make_float2(acc[i][j][0], acc[i][j][1]);
            float2 v1 = make_float2(acc[i][j][2], acc[i][j][3]);
            if (EPI & 1) {
                float2 bb = *(const float2*)(bias + n0);
                v0.x += bb.x; v0.y += bb.y; v1.x += bb.x; v1.y += bb.y;
            }
            if (EPI & 2) {
                v0.x = fmaxf(v0.x, 0.f); v0.y = fmaxf(v0.y, 0.f);
                v1.x = fmaxf(v1.x, 0.f); v1.y = fmaxf(v1.y, 0.f);
            }
            if (EPI & 4) {
                float2 r0 = *(const float2*)(res + (size_t)m0 * N + n0);
                float2 r1 = *(const float2*)(res + (size_t)(m0 + 8) * N + n0);
                v0.x += r0.x; v0.y += r0.y; v1.x += r1.x; v1.y += r1.y;
            }
            if (EPI & 8) {
                v0.x = rtf32(v0.x); v0.y = rtf32(v0.y);
                v1.x = rtf32(v1.x); v1.y = rtf32(v1.y);
            }
            *(float2*)(Dm + (size_t)m0 * N + n0) = v0;
            *(float2*)(Dm + (size_t)(m0 + 8) * N + n0) = v1;
        }
    }
}

// ---------------- causal flash attention (SIMT), qkv fused layout -----------
// qkv layout: [b*T + t][3072]; q at col h*64, k at 1024 + h*64, v at 2048 + h*64
__global__ void __launch_bounds__(256) attn_kernel(
    const float* __restrict__ QKV, float* __restrict__ O)
{
    __shared__ float Qs[64][64];
    __shared__ float Ks[64][64];   // reused as P
    __shared__ float Vs[64][64];

    const int bh = blockIdx.x, qt = blockIdx.y;
    const int b = bh >> 4, h = bh & 15;
    const float* Qb = QKV + (size_t)b * T_ * C3_ + h * 64;
    const float* Kb = Qb + 1024;
    const float* Vb = Qb + 2048;
    float* Ob = O + (size_t)b * T_ * C_ + h * 64;

    const int tid = threadIdx.x;
    const int tr = (tid >> 4) << 2;
    const int tc = (tid & 15) << 2;

    #pragma unroll
    for (int i = 0; i < 4; i++) {
        int idx = i * 256 + tid;
        int row = idx >> 4, c4 = (idx & 15) << 2;
        float4 qv = *(const float4*)(Qb + (size_t)(qt * 64 + row) * C3_ + c4);
        Qs[c4 + 0][row] = qv.x; Qs[c4 + 1][row] = qv.y;
        Qs[c4 + 2][row] = qv.z; Qs[c4 + 3][row] = qv.w;
    }

    float m[4], l[4], acc[4][4];
    #pragma unroll
    for (int i = 0; i < 4; i++) {
        m[i] = -INFINITY; l[i] = 0.f;
        #pragma unroll
        for (int j = 0; j < 4; j++) acc[i][j] = 0.f;
    }

    for (int kt = 0; kt <= qt; kt++) {
        __syncthreads();
        #pragma unroll
        for (int i = 0; i < 4; i++) {
            int idx = i * 256 + tid;
            int row = idx >> 4, c4 = (idx & 15) << 2;
            float4 kv = *(const float4*)(Kb + (size_t)(kt * 64 + row) * C3_ + c4);
            Ks[c4 + 0][row] = kv.x; Ks[c4 + 1][row] = kv.y;
            Ks[c4 + 2][row] = kv.z; Ks[c4 + 3][row] = kv.w;
            float4 vv = *(const float4*)(Vb + (size_t)(kt * 64 + row) * C3_ + c4);
            *(float4*)&Vs[row][c4] = vv;
        }
        __syncthreads();

        float s[4][4];
        #pragma unroll
        for (int i = 0; i < 4; i++)
            #pragma unroll
            for (int j = 0; j < 4; j++) s[i][j] = 0.f;
        #pragma unroll 16
        for (int kk = 0; kk < 64; kk++) {
            float4 q4 = *(const float4*)&Qs[kk][tr];
            float4 k4 = *(const float4*)&Ks[kk][tc];
            float qa[4] = {q4.x, q4.y, q4.z, q4.w};
            float ka[4] = {k4.x, k4.y, k4.z, k4.w};
            #pragma unroll
            for (int i = 0; i < 4; i++)
                #pragma unroll
                for (int j = 0; j < 4; j++)
                    s[i][j] += qa[i] * ka[j];
        }

        float p[4][4];
        const float scale = 0.03125f;
        #pragma unroll
        for (int i = 0; i < 4; i++) {
            float mx = -INFINITY;
            #pragma unroll
            for (int j = 0; j < 4; j++) {
                float sv = s[i][j] * scale;
                if (kt == qt && (tc + j) > (tr + i)) sv = -INFINITY;
                s[i][j] = sv;
                mx = fmaxf(mx, sv);
            }
            #pragma unroll
            for (int off = 1; off < 16; off <<= 1)
                mx = fmaxf(mx, __shfl_xor_sync(0xffffffffu, mx, off, 16));
            float mn = fmaxf(m[i], mx);
            float a = __expf(m[i] - mn);
            m[i] = mn;
            float rs = 0.f;
            #pragma unroll
            for (int j = 0; j < 4; j++) {
                float pv = __expf(s[i][j] - mn);
                p[i][j] = pv; rs += pv;
            }
            #pragma unroll
            for (int off = 1; off < 16; off <<= 1)
                rs += __shfl_xor_sync(0xffffffffu, rs, off, 16);
            l[i] = l[i] * a + rs;
            #pragma unroll
            for (int j = 0; j < 4; j++) acc[i][j] *= a;
        }

        __syncthreads();
        #pragma unroll
        for (int i = 0; i < 4; i++)
            *(float4*)&Ks[tr + i][tc] = make_float4(p[i][0], p[i][1], p[i][2], p[i][3]);
        __syncwarp();

        #pragma unroll 8
        for (int j = 0; j < 64; j++) {
            float4 v4 = *(const float4*)&Vs[j][tc];
            #pragma unroll
            for (int i = 0; i < 4; i++) {
                float pv = Ks[tr + i][j];
                acc[i][0] += pv * v4.x;
                acc[i][1] += pv * v4.y;
                acc[i][2] += pv * v4.z;
                acc[i][3] += pv * v4.w;
            }
        }
    }

    #pragma unroll
    for (int i = 0; i < 4; i++) {
        float inv = 1.0f / l[i];
        float4 o = make_float4(rtf32(acc[i][0] * inv), rtf32(acc[i][1] * inv),
                               rtf32(acc[i][2] * inv), rtf32(acc[i][3] * inv));
        *(float4*)(Ob + (size_t)(qt * 64 + tr + i) * C_ + tc) = o;
    }
}

// ---------------------------------------------------------------------------
extern "C" void kernel_launch(void* const* d_in, const int* in_sizes, int n_in,
                              void* d_out, int out_size)
{
    const float* x      = (const float*)d_in[0];
    const float* wq     = (const float*)d_in[1];
    const float* wk     = (const float*)d_in[2];
    const float* wv     = (const float*)d_in[3];
    const float* w_proj = (const float*)d_in[4];
    const float* b_proj = (const float*)d_in[5];
    const float* w1     = (const float*)d_in[6];
    const float* b1     = (const float*)d_in[7];
    const float* w2     = (const float*)d_in[8];
    const float* b2     = (const float*)d_in[9];
    const float* g1     = (const float*)d_in[10];
    const float* be1    = (const float*)d_in[11];
    const float* g2     = (const float*)d_in[12];
    const float* be2    = (const float*)d_in[13];
    float* out = (float*)d_out;

    float *xn, *qkv, *att, *x1, *xn2, *hb, *pw, *wpt, *w1t, *w2t;
    cudaGetSymbolAddress((void**)&xn,  g_xn);
    cudaGetSymbolAddress((void**)&qkv, g_qkv);
    cudaGetSymbolAddress((void**)&att, g_att);
    cudaGetSymbolAddress((void**)&x1,  g_x1);
    cudaGetSymbolAddress((void**)&xn2, g_xn2);
    cudaGetSymbolAddress((void**)&hb,  g_h);
    cudaGetSymbolAddress((void**)&pw,  g_pw);
    cudaGetSymbolAddress((void**)&wpt, g_wpt);
    cudaGetSymbolAddress((void**)&w1t, g_w1t);
    cudaGetSymbolAddress((void**)&w2t, g_w2t);

    cudaFuncSetAttribute(gemm_mma<0>,  cudaFuncAttributeMaxDynamicSharedMemorySize, GSMEM);
    cudaFuncSetAttribute(gemm_mma<5>,  cudaFuncAttributeMaxDynamicSharedMemorySize, GSMEM);
    cudaFuncSetAttribute(gemm_mma<11>, cudaFuncAttributeMaxDynamicSharedMemorySize, GSMEM);

    dim3 tb(32, 8);
    // weight transposes to K-major [N][K], rounded to tf32
    transpose_k<<<dim3(2, 32, 16), tb>>>(wq, pw,               C_, D_);
    transpose_k<<<dim3(2, 32, 16), tb>>>(wk, pw + C_ * C_,     C_, D_);
    transpose_k<<<dim3(2, 32, 16), tb>>>(wv, pw + 2 * C_ * C_, C_, D_);
    transpose_k<<<dim3(32, 32, 1),  tb>>>(w_proj, wpt, C_, C_);
    transpose_k<<<dim3(128, 32, 1), tb>>>(w1, w1t, C_, F_);
    transpose_k<<<dim3(32, 128, 1), tb>>>(w2, w2t, F_, C_);

    // LN1 (tf32-rounded output)
    ln_kernel<<<M_, 256>>>(x, g1, be1, xn);
    // fused QKV projection: [8192, 3072] (fp32 output for attention)
    gemm_mma<0><<<dim3(C3_ / BN, M_ / BM), 256, GSMEM>>>(xn, pw, qkv, nullptr, nullptr, M_, C3_, C_);
    // causal attention (tf32-rounded output)
    attn_kernel<<<dim3(B_ * H_, T_ / 64), 256>>>(qkv, att);
    // out projection + bias + residual(x) (fp32 output)
    gemm_mma<5><<<dim3(C_ / BN, M_ / BM), 256, GSMEM>>>(att, wpt, x1, b_proj, x, M_, C_, C_);
    // LN2 (tf32-rounded output)
    ln_kernel<<<M_, 256>>>(x1, g2, be2, xn2);
    // FFN1: bias + relu + tf32-round (feeds FFN2)
    gemm_mma<11><<<dim3(F_ / BN, M_ / BM), 256, GSMEM>>>(xn2, w1t, hb, b1, nullptr, M_, F_, C_);
    // FFN2: bias + residual(x1) -> out (fp32)
    gemm_mma<5><<<dim3(C_ / BN, M_ / BM), 256, GSMEM>>>(hb, w2t, out, b2, x1, M_, C_, F_);
}

// round 6
// speedup vs baseline: 3.1892x; 1.3952x over previous
#include <cuda_runtime.h>
#include <math.h>
#include <stdint.h>

#define B_ 4
#define T_ 2048
#define C_ 1024
#define H_ 16
#define D_ 64
#define M_ (B_*T_)      // 8192 rows
#define F_ (4*C_)       // 4096 ffn hidden
#define C3_ 3072        // fused qkv width

// ---------------- scratch (device globals; no allocations allowed) ----------
__device__ __align__(256) float g_xn  [M_*C_];
__device__ __align__(256) float g_qkv [M_*C3_];
__device__ __align__(256) float g_att [M_*C_];
__device__ __align__(256) float g_x1  [M_*C_];
__device__ __align__(256) float g_xn2 [M_*C_];
__device__ __align__(256) float g_h   [M_*F_];
__device__ __align__(256) float g_pw  [C3_*C_];   // fused qkv weights [3072][1024] K-major
__device__ __align__(256) float g_wpt [C_*C_];    // w_proj^T
__device__ __align__(256) float g_w1t [F_*C_];    // w1^T
__device__ __align__(256) float g_w2t [C_*F_];    // w2^T

// ======================= helpers =======================
__device__ __forceinline__ uint32_t smem_u32(const void* p) {
    uint32_t a;
    asm("{ .reg .u64 t; cvta.to.shared.u64 t, %1; cvt.u32.u64 %0, t; }" : "=r"(a) : "l"(p));
    return a;
}
__device__ __forceinline__ float rtf32(float x) {
    uint32_t u;
    asm("cvt.rna.tf32.f32 %0, %1;" : "=r"(u) : "f"(x));
    return __uint_as_float(u);
}
__device__ __forceinline__ void cp16(uint32_t dst, const void* src) {
    asm volatile("cp.async.cg.shared.global [%0], [%1], 16;" :: "r"(dst), "l"(src));
}
__device__ __forceinline__ void mma_tf32_frag(float* c, const uint32_t* a, uint32_t b0, uint32_t b1) {
    asm volatile(
        "mma.sync.aligned.m16n8k8.row.col.f32.tf32.tf32.f32 "
        "{%0,%1,%2,%3}, {%4,%5,%6,%7}, {%8,%9}, {%0,%1,%2,%3};\n"
        : "+f"(c[0]), "+f"(c[1]), "+f"(c[2]), "+f"(c[3])
        : "r"(a[0]), "r"(a[1]), "r"(a[2]), "r"(a[3]), "r"(b0), "r"(b1));
}

// ======================= LayerNorm (rounds output to tf32) =======
__global__ void ln_kernel(const float* __restrict__ x, const float* __restrict__ g,
                          const float* __restrict__ b, float* __restrict__ out)
{
    const int row = blockIdx.x, tid = threadIdx.x;
    float4 xv = ((const float4*)(x + (size_t)row * C_))[tid];
    __shared__ float r1[8], r2[8];

    float s = xv.x + xv.y + xv.z + xv.w;
    #pragma unroll
    for (int o = 16; o > 0; o >>= 1) s += __shfl_xor_sync(0xffffffffu, s, o);
    if ((tid & 31) == 0) r1[tid >> 5] = s;
    __syncthreads();
    float mu = (r1[0]+r1[1]+r1[2]+r1[3]+r1[4]+r1[5]+r1[6]+r1[7]) * (1.0f / C_);

    float d0 = xv.x - mu, d1 = xv.y - mu, d2 = xv.z - mu, d3 = xv.w - mu;
    float sq = d0*d0 + d1*d1 + d2*d2 + d3*d3;
    #pragma unroll
    for (int o = 16; o > 0; o >>= 1) sq += __shfl_xor_sync(0xffffffffu, sq, o);
    if ((tid & 31) == 0) r2[tid >> 5] = sq;
    __syncthreads();
    float rstd = rsqrtf((r2[0]+r2[1]+r2[2]+r2[3]+r2[4]+r2[5]+r2[6]+r2[7]) * (1.0f / C_) + 1e-5f);

    float4 gv = ((const float4*)g)[tid];
    float4 bv = ((const float4*)b)[tid];
    float4 o4;
    o4.x = rtf32(d0 * rstd * gv.x + bv.x);
    o4.y = rtf32(d1 * rstd * gv.y + bv.y);
    o4.z = rtf32(d2 * rstd * gv.z + bv.z);
    o4.w = rtf32(d3 * rstd * gv.w + bv.w);
    ((float4*)(out + (size_t)row * C_))[tid] = o4;
}

// ========== batched transpose: in[b][R][Cc] -> out[(b*Cc + c)*R + r], tf32-rounded ==========
__global__ void transpose_k(const float* __restrict__ in, float* __restrict__ out, int R, int Cc)
{
    __shared__ float t[32][33];
    const int b = blockIdx.z;
    const float* ib = in + (size_t)b * R * Cc;
    float* ob = out + (size_t)b * Cc * R;
    const int c0 = blockIdx.x * 32, r0 = blockIdx.y * 32;
    const int tx = threadIdx.x, ty = threadIdx.y;
    #pragma unroll
    for (int j = 0; j < 32; j += 8)
        t[ty + j][tx] = ib[(size_t)(r0 + ty + j) * Cc + c0 + tx];
    __syncthreads();
    #pragma unroll
    for (int j = 0; j < 32; j += 8)
        ob[(size_t)(c0 + ty + j) * R + r0 + tx] = rtf32(t[tx][ty + j]);
}

// ======================= tf32 mma.sync GEMM =======================
// D[M,N] = A[M,K] @ Bt[N,K]^T ; CTA tile 128x256, 8 warps (2x4), warp tile 64x64
// EPI bits: 1=+bias, 2=relu, 4=+residual, 8=round output to tf32
#define BM 128
#define BN 256
#define BKG 32
#define STR 36
#define ABUF (BM*STR)
#define BUFW ((BM+BN)*STR)
#define GSMEM (2*BUFW*4)

template<int EPI>
__global__ void __launch_bounds__(256, 1) gemm_mma(
    const float* __restrict__ A, const float* __restrict__ Bt,
    float* __restrict__ Dm, const float* __restrict__ bias,
    const float* __restrict__ res, int M, int N, int K)
{
    extern __shared__ __align__(16) float sm[];
    const uint32_t sbase = smem_u32(sm);
    const int tid = threadIdx.x;
    const int wid = tid >> 5, lane = tid & 31;
    const int wm = (wid >> 2) * 64, wn = (wid & 3) * 64;
    const int g = lane >> 2, t = lane & 3;

    uint32_t gofs[12], sofs[12];
    #pragma unroll
    for (int s = 0; s < 12; s++) {
        int sid = s * 256 + tid;
        if (s < 4) {
            int row = sid >> 3, seg = sid & 7;
            gofs[s] = (uint32_t)((blockIdx.y * BM + row) * K + seg * 4);
            sofs[s] = (uint32_t)((row * STR + seg * 4) * 4);
        } else {
            int row = (sid - 1024) >> 3, seg = sid & 7;
            gofs[s] = (uint32_t)((blockIdx.x * BN + row) * K + seg * 4);
            sofs[s] = (uint32_t)(((BM + row) * STR + seg * 4) * 4);
        }
    }

    float acc[4][8][4];
    #pragma unroll
    for (int i = 0; i < 4; i++)
        #pragma unroll
        for (int j = 0; j < 8; j++)
            #pragma unroll
            for (int q = 0; q < 4; q++) acc[i][j][q] = 0.f;

    const int NIT = K / BKG;

    {
        uint32_t db = sbase;
        #pragma unroll
        for (int s = 0; s < 4; s++)  cp16(db + sofs[s], A  + gofs[s]);
        #pragma unroll
        for (int s = 4; s < 12; s++) cp16(db + sofs[s], Bt + gofs[s]);
        asm volatile("cp.async.commit_group;");
    }

    #pragma unroll 1
    for (int it = 0; it < NIT; it++) {
        const int p = it & 1;
        if (it + 1 < NIT) {
            uint32_t db = sbase + (p ^ 1) * (BUFW * 4);
            uint32_t ko = (uint32_t)((it + 1) * BKG);
            #pragma unroll
            for (int s = 0; s < 4; s++)  cp16(db + sofs[s], A  + gofs[s] + ko);
            #pragma unroll
            for (int s = 4; s < 12; s++) cp16(db + sofs[s], Bt + gofs[s] + ko);
        }
        asm volatile("cp.async.commit_group;");
        asm volatile("cp.async.wait_group 1;");
        __syncthreads();

        const float* Ab = sm + p * BUFW;
        const float* Bb = Ab + ABUF;
        #pragma unroll
        for (int ks = 0; ks < 4; ks++) {
            const int k0 = ks * 8 + t;
            uint32_t a[4][4];
            #pragma unroll
            for (int i = 0; i < 4; i++) {
                const float* ap = Ab + (wm + i * 16 + g) * STR + k0;
                a[i][0] = __float_as_uint(ap[0]);
                a[i][1] = __float_as_uint(ap[8 * STR]);
                a[i][2] = __float_as_uint(ap[4]);
                a[i][3] = __float_as_uint(ap[8 * STR + 4]);
            }
            #pragma unroll
            for (int j = 0; j < 8; j++) {
                const float* bp = Bb + (wn + j * 8 + g) * STR + k0;
                uint32_t b0 = __float_as_uint(bp[0]);
                uint32_t b1 = __float_as_uint(bp[4]);
                #pragma unroll
                for (int i = 0; i < 4; i++)
                    mma_tf32_frag(acc[i][j], a[i], b0, b1);
            }
        }
        __syncthreads();
    }

    #pragma unroll
    for (int i = 0; i < 4; i++) {
        const int m0 = blockIdx.y * BM + wm + i * 16 + g;
        #pragma unroll
        for (int j = 0; j < 8; j++) {
            const int n0 = blockIdx.x * BN + wn + j * 8 + t * 2;
            float2 v0 = make_float2(acc[i][j][0], acc[i][j][1]);
            float2 v1 = make_float2(acc[i][j][2], acc[i][j][3]);
            if (EPI & 1) {
                float2 bb = *(const float2*)(bias + n0);
                v0.x += bb.x; v0.y += bb.y; v1.x += bb.x; v1.y += bb.y;
            }
            if (EPI & 2) {
                v0.x = fmaxf(v0.x, 0.f); v0.y = fmaxf(v0.y, 0.f);
                v1.x = fmaxf(v1.x, 0.f); v1.y = fmaxf(v1.y, 0.f);
            }
            if (EPI & 4) {
                float2 r0 = *(const float2*)(res + (size_t)m0 * N + n0);
                float2 r1 = *(const float2*)(res + (size_t)(m0 + 8) * N + n0);
                v0.x += r0.x; v0.y += r0.y; v1.x += r1.x; v1.y += r1.y;
            }
            if (EPI & 8) {
                v0.x = rtf32(v0.x); v0.y = rtf32(v0.y);
                v1.x = rtf32(v1.x); v1.y = rtf32(v1.y);
            }
            *(float2*)(Dm + (size_t)m0 * N + n0) = v0;
            *(float2*)(Dm + (size_t)(m0 + 8) * N + n0) = v1;
        }
    }
}

// =============== tensor-core causal flash attention (tf32 mma.sync) ==========
// q-tile 128 x kv-tile 64; 8 warps, each warp owns 16 q-rows x 64 cols.
// Q/K/V are exact tf32 (QKV gemm rounds). P rounded to tf32 before PV.
#define ASTR 68                         // 68 mod 32 = 4 -> 4g+t conflict-free
#define AQ_OFF 0                        // Qs 128 x 68
#define AK_OFF (128*ASTR)               // Ks 64 x 68
#define AV_OFF (AK_OFF + 64*ASTR)       // Vt 64 x 68  (d-major: Vt[d][s])
#define AP_OFF (AV_OFF + 64*ASTR)       // Ps 128 x 68
#define ASMEM ((AP_OFF + 128*ASTR) * 4) // 104448 bytes

__global__ void __launch_bounds__(256, 1) attn_mma(
    const float* __restrict__ QKV, float* __restrict__ O)
{
    extern __shared__ __align__(16) float as_[];
    float* Qs = as_ + AQ_OFF;
    float* Ks = as_ + AK_OFF;
    float* Vt = as_ + AV_OFF;
    float* Ps = as_ + AP_OFF;

    const int bh = blockIdx.x, qt = blockIdx.y;
    const int b = bh >> 4, h = bh & 15;
    const float* Qb = QKV + (size_t)b * T_ * C3_ + h * 64;
    const float* Kb = Qb + 1024;
    const float* Vb = Qb + 2048;
    float* Ob = O + (size_t)b * T_ * C_ + h * 64;

    const int tid = threadIdx.x;
    const int wid = tid >> 5, lane = tid & 31;
    const int g = lane >> 2, t = lane & 3;
    const int row0 = wid * 16;

    // load Q tile: 128 rows x 64 cols
    #pragma unroll
    for (int i = 0; i < 8; i++) {
        int idx = i * 256 + tid;
        int row = idx >> 4, c4 = (idx & 15) << 2;
        float4 qv = *(const float4*)(Qb + (size_t)(qt * 128 + row) * C3_ + c4);
        *(float4*)&Qs[row * ASTR + c4] = qv;
    }

    float m0 = -INFINITY, m1 = -INFINITY, l0 = 0.f, l1 = 0.f;
    float o[8][4];
    #pragma unroll
    for (int nf = 0; nf < 8; nf++)
        #pragma unroll
        for (int c = 0; c < 4; c++) o[nf][c] = 0.f;

    const int rqA = qt * 128 + row0 + g;
    const int rqB = rqA + 8;
    const int ktmax = 2 * qt + 1;

    #pragma unroll 1
    for (int kt = 0; kt <= ktmax; kt++) {
        __syncthreads();   // prior iter done reading Ks/Vt (and Q stores on iter 0)
        #pragma unroll
        for (int i = 0; i < 4; i++) {
            int idx = i * 256 + tid;
            int row = idx >> 4, c4 = (idx & 15) << 2;
            float4 kv = *(const float4*)(Kb + (size_t)(kt * 64 + row) * C3_ + c4);
            *(float4*)&Ks[row * ASTR + c4] = kv;
            float4 vv = *(const float4*)(Vb + (size_t)(kt * 64 + row) * C3_ + c4);
            Vt[(c4 + 0) * ASTR + row] = vv.x;
            Vt[(c4 + 1) * ASTR + row] = vv.y;
            Vt[(c4 + 2) * ASTR + row] = vv.z;
            Vt[(c4 + 3) * ASTR + row] = vv.w;
        }
        __syncthreads();

        // S = Q K^T  (16 x 64 per warp, k = d = 64)
        float s[8][4];
        #pragma unroll
        for (int nf = 0; nf < 8; nf++)
            #pragma unroll
            for (int c = 0; c < 4; c++) s[nf][c] = 0.f;
        #pragma unroll
        for (int ks = 0; ks < 8; ks++) {
            const int k0 = ks * 8 + t;
            uint32_t a[4];
            const float* ap = Qs + (row0 + g) * ASTR + k0;
            a[0] = __float_as_uint(ap[0]);
            a[1] = __float_as_uint(ap[8 * ASTR]);
            a[2] = __float_as_uint(ap[4]);
            a[3] = __float_as_uint(ap[8 * ASTR + 4]);
            #pragma unroll
            for (int nf = 0; nf < 8; nf++) {
                const float* bp = Ks + (nf * 8 + g) * ASTR + k0;
                mma_tf32_frag(s[nf], a, __float_as_uint(bp[0]), __float_as_uint(bp[4]));
            }
        }

        // scale + causal mask + online softmax
        const float scale = 0.03125f;
        const int colbase = kt * 64 + t * 2;
        float mxA = -INFINITY, mxB = -INFINITY;
        #pragma unroll
        for (int nf = 0; nf < 8; nf++) {
            #pragma unroll
            for (int c = 0; c < 2; c++) {
                int col = colbase + nf * 8 + c;
                float vA = s[nf][c] * scale;     if (col > rqA) vA = -INFINITY;
                float vB = s[nf][2 + c] * scale; if (col > rqB) vB = -INFINITY;
                s[nf][c] = vA; s[nf][2 + c] = vB;
                mxA = fmaxf(mxA, vA); mxB = fmaxf(mxB, vB);
            }
        }
        mxA = fmaxf(mxA, __shfl_xor_sync(0xffffffffu, mxA, 1));
        mxA = fmaxf(mxA, __shfl_xor_sync(0xffffffffu, mxA, 2));
        mxB = fmaxf(mxB, __shfl_xor_sync(0xffffffffu, mxB, 1));
        mxB = fmaxf(mxB, __shfl_xor_sync(0xffffffffu, mxB, 2));

        float mnA = fmaxf(m0, mxA), mnB = fmaxf(m1, mxB);
        float fA = __expf(m0 - mnA), fB = __expf(m1 - mnB);
        m0 = mnA; m1 = mnB;
        float rsA = 0.f, rsB = 0.f;
        #pragma unroll
        for (int nf = 0; nf < 8; nf++) {
            #pragma unroll
            for (int c = 0; c < 2; c++) {
                float pA = __expf(s[nf][c] - mnA);
                float pB = __expf(s[nf][2 + c] - mnB);
                s[nf][c] = pA; s[nf][2 + c] = pB;
                rsA += pA; rsB += pB;
            }
            o[nf][0] *= fA; o[nf][1] *= fA;
            o[nf][2] *= fB; o[nf][3] *= fB;
        }
        rsA += __shfl_xor_sync(0xffffffffu, rsA, 1);
        rsA += __shfl_xor_sync(0xffffffffu, rsA, 2);
        rsB += __shfl_xor_sync(0xffffffffu, rsB, 1);
        rsB += __shfl_xor_sync(0xffffffffu, rsB, 2);
        l0 = l0 * fA + rsA;
        l1 = l1 * fB + rsB;

        // P (tf32-rounded) -> smem (warp-private rows)
        #pragma unroll
        for (int nf = 0; nf < 8; nf++) {
            *(float2*)&Ps[(row0 + g) * ASTR + nf * 8 + t * 2] =
                make_float2(rtf32(s[nf][0]), rtf32(s[nf][1]));
            *(float2*)&Ps[(row0 + g + 8) * ASTR + nf * 8 + t * 2] =
                make_float2(rtf32(s[nf][2]), rtf32(s[nf][3]));
        }
        __syncwarp();

        // O += P @ V   (k = s = 64; B = Vt[d][s])
        #pragma unroll
        for (int ks = 0; ks < 8; ks++) {
            const int k0 = ks * 8 + t;
            uint32_t a[4];
            const float* ap = Ps + (row0 + g) * ASTR + k0;
            a[0] = __float_as_uint(ap[0]);
            a[1] = __float_as_uint(ap[8 * ASTR]);
            a[2] = __float_as_uint(ap[4]);
            a[3] = __float_as_uint(ap[8 * ASTR + 4]);
            #pragma unroll
            for (int nf = 0; nf < 8; nf++) {
                const float* bp = Vt + (nf * 8 + g) * ASTR + k0;
                mma_tf32_frag(o[nf], a, __float_as_uint(bp[0]), __float_as_uint(bp[4]));
            }
        }
    }

    const float i0 = 1.0f / l0, i1 = 1.0f / l1;
    #pragma unroll
    for (int nf = 0; nf < 8; nf++) {
        int col = nf * 8 + t * 2;
        *(float2*)(Ob + (size_t)(qt * 128 + row0 + g) * C_ + col) =
            make_float2(rtf32(o[nf][0] * i0), rtf32(o[nf][1] * i0));
        *(float2*)(Ob + (size_t)(qt * 128 + row0 + g + 8) * C_ + col) =
            make_float2(rtf32(o[nf][2] * i1), rtf32(o[nf][3] * i1));
    }
}

// ---------------------------------------------------------------------------
extern "C" void kernel_launch(void* const* d_in, const int* in_sizes, int n_in,
                              void* d_out, int out_size)
{
    const float* x      = (const float*)d_in[0];
    const float* wq     = (const float*)d_in[1];
    const float* wk     = (const float*)d_in[2];
    const float* wv     = (const float*)d_in[3];
    const float* w_proj = (const float*)d_in[4];
    const float* b_proj = (const float*)d_in[5];
    const float* w1     = (const float*)d_in[6];
    const float* b1     = (const float*)d_in[7];
    const float* w2     = (const float*)d_in[8];
    const float* b2     = (const float*)d_in[9];
    const float* g1     = (const float*)d_in[10];
    const float* be1    = (const float*)d_in[11];
    const float* g2     = (const float*)d_in[12];
    const float* be2    = (const float*)d_in[13];
    float* out = (float*)d_out;

    float *xn, *qkv, *att, *x1, *xn2, *hb, *pw, *wpt, *w1t, *w2t;
    cudaGetSymbolAddress((void**)&xn,  g_xn);
    cudaGetSymbolAddress((void**)&qkv, g_qkv);
    cudaGetSymbolAddress((void**)&att, g_att);
    cudaGetSymbolAddress((void**)&x1,  g_x1);
    cudaGetSymbolAddress((void**)&xn2, g_xn2);
    cudaGetSymbolAddress((void**)&hb,  g_h);
    cudaGetSymbolAddress((void**)&pw,  g_pw);
    cudaGetSymbolAddress((void**)&wpt, g_wpt);
    cudaGetSymbolAddress((void**)&w1t, g_w1t);
    cudaGetSymbolAddress((void**)&w2t, g_w2t);

    cudaFuncSetAttribute(gemm_mma<8>,  cudaFuncAttributeMaxDynamicSharedMemorySize, GSMEM);
    cudaFuncSetAttribute(gemm_mma<5>,  cudaFuncAttributeMaxDynamicSharedMemorySize, GSMEM);
    cudaFuncSetAttribute(gemm_mma<11>, cudaFuncAttributeMaxDynamicSharedMemorySize, GSMEM);
    cudaFuncSetAttribute(attn_mma,     cudaFuncAttributeMaxDynamicSharedMemorySize, ASMEM);

    dim3 tb(32, 8);
    // weight transposes to K-major [N][K], rounded to tf32
    transpose_k<<<dim3(2, 32, 16), tb>>>(wq, pw,               C_, D_);
    transpose_k<<<dim3(2, 32, 16), tb>>>(wk, pw + C_ * C_,     C_, D_);
    transpose_k<<<dim3(2, 32, 16), tb>>>(wv, pw + 2 * C_ * C_, C_, D_);
    transpose_k<<<dim3(32, 32, 1),  tb>>>(w_proj, wpt, C_, C_);
    transpose_k<<<dim3(128, 32, 1), tb>>>(w1, w1t, C_, F_);
    transpose_k<<<dim3(32, 128, 1), tb>>>(w2, w2t, F_, C_);

    // LN1 (tf32-rounded output)
    ln_kernel<<<M_, 256>>>(x, g1, be1, xn);
    // fused QKV projection, tf32-rounded output (feeds tensor-core attention)
    gemm_mma<8><<<dim3(C3_ / BN, M_ / BM), 256, GSMEM>>>(xn, pw, qkv, nullptr, nullptr, M_, C3_, C_);
    // causal attention on tensor cores (tf32-rounded output)
    attn_mma<<<dim3(B_ * H_, T_ / 128), 256, ASMEM>>>(qkv, att);
    // out projection + bias + residual(x)
    gemm_mma<5><<<dim3(C_ / BN, M_ / BM), 256, GSMEM>>>(att, wpt, x1, b_proj, x, M_, C_, C_);
    // LN2 (tf32-rounded output)
    ln_kernel<<<M_, 256>>>(x1, g2, be2, xn2);
    // FFN1: bias + relu + tf32-round (feeds FFN2)
    gemm_mma<11><<<dim3(F_ / BN, M_ / BM), 256, GSMEM>>>(xn2, w1t, hb, b1, nullptr, M_, F_, C_);
    // FFN2: bias + residual(x1) -> out
    gemm_mma<5><<<dim3(C_ / BN, M_ / BM), 256, GSMEM>>>(hb, w2t, out, b2, x1, M_, C_, F_);
}